// round 14
// baseline (speedup 1.0000x reference)
#include <cuda_runtime.h>
#include <math.h>

#define J 20
#define JPS 5
#define CPJ 111          // floats per joint (odd -> conflict-free broadcast)
#define REGSZ 384
// layout per joint (float offsets):
//   0:M0[9] 9:M1[9] 18:M2[9] 27:M0p[9] 36:M1p[9] 45:M2p[9]
//  54:M0t[9] 63:M1t[9] 72:M2t[9]
//  81:d0[3] 84:d1[3] 87:d2[3] 90:e0[3] 93:e1[3] 96:e2[3]
//  99:f0[3] 102:f1[3] 105:f2[3] 108:p_rev[3]

__device__ __forceinline__ void rpy2r_fast(float r, float p, float y, float* R) {
    float cr, sr, cp, sp, cy, sy;
    __sincosf(r, &sr, &cr);
    __sincosf(p, &sp, &cp);
    __sincosf(y, &sy, &cy);
    R[0] = cy * cp; R[1] = cy * sp * sr - sy * cr; R[2] = cy * sp * cr + sy * sr;
    R[3] = sy * cp; R[4] = sy * sp * sr + cy * cr; R[5] = sy * sp * cr - cy * sr;
    R[6] = -sp;     R[7] = cp * sr;                R[8] = cp * cr;
}

__device__ __forceinline__ void mm3(float* D, const float* A, const float* B) {
#pragma unroll
    for (int r = 0; r < 3; r++)
#pragma unroll
        for (int c = 0; c < 3; c++)
            D[r * 3 + c] = fmaf(A[r * 3 + 0], B[0 * 3 + c],
                           fmaf(A[r * 3 + 1], B[1 * 3 + c],
                                A[r * 3 + 2] * B[2 * 3 + c]));
}

// D = Ca + s*Cb + ic*Cc (9 elements from shared)
__device__ __forceinline__ void fold9(float* D, const float* C, int a, int b, int c,
                                      float s, float ic) {
#pragma unroll
    for (int i = 0; i < 9; i++)
        D[i] = fmaf(s, C[b + i], fmaf(ic, C[c + i], C[a + i]));
}

// w = R@u + p
__device__ __forceinline__ void matvec_add(float* w, const float* R, const float* u,
                                           const float* p) {
#pragma unroll
    for (int r = 0; r < 3; r++)
        w[r] = fmaf(R[r*3+0], u[0], fmaf(R[r*3+1], u[1], fmaf(R[r*3+2], u[2], p[r])));
}

__device__ __forceinline__ void stage12(float* dst, const float R[9], const float p[3]) {
    float4* sp = (float4*)dst;
    sp[0] = make_float4(R[0], R[1], R[2], p[0]);
    sp[1] = make_float4(R[3], R[4], R[5], p[1]);
    sp[2] = make_float4(R[6], R[7], R[8], p[2]);
}

__global__ void __launch_bounds__(128, 7)
fk_kernel(const float* __restrict__ rev_q, const float* __restrict__ pri_q,
          const float* __restrict__ rev_p_off, const float* __restrict__ rev_rpy_off,
          const float* __restrict__ pri_p_off, const float* __restrict__ pri_rpy_off,
          const float* __restrict__ rev_axis, const float* __restrict__ pri_axis,
          const float* __restrict__ p_track, const float* __restrict__ rpy_track,
          float* __restrict__ out, int B) {
    __shared__ float sC[J * CPJ];
    __shared__ float sStage[4][3 * REGSZ];

    int tid  = threadIdx.x;
    int lane = tid & 31;
    int w    = tid >> 5;
    int bb   = lane >> 2;
    int s    = lane & 3;
    int wb0  = blockIdx.x * 32 + w * 8;
    int gb   = wb0 + bb; if (gb >= B) gb = B - 1;

    // q loads + trig early (cached in regs, R12-style)
    float sn[JPS], ic[JPS], qp[JPS];
#pragma unroll
    for (int i = 0; i < JPS; i++) {
        float q = rev_q[(size_t)gb * J + s * JPS + i];
        float c;
        __sincosf(q, &sn[i], &c);
        ic[i] = 1.f - c;
        qp[i] = pri_q[(size_t)gb * J + s * JPS + i];
    }

    // ---- in-block constant prep (threads 0..19) ----
    if (tid < J) {
        int j = tid;
        float* C = sC + j * CPJ;
        float M0[9];
        rpy2r_fast(rev_rpy_off[j*3+0], rev_rpy_off[j*3+1], rev_rpy_off[j*3+2], M0);
        float ax = rev_axis[j*3+0], ay = rev_axis[j*3+1], az = rev_axis[j*3+2];
        float n = sqrtf(ax*ax + ay*ay + az*az) + 1e-12f;
        ax /= n; ay /= n; az /= n;
        float K[9]  = {0.f, -az, ay,  az, 0.f, -ax,  -ay, ax, 0.f};
        float K2[9]; mm3(K2, K, K);
        float M1[9], M2[9]; mm3(M1, M0, K); mm3(M2, M0, K2);

        float Rp[9];
        rpy2r_fast(pri_rpy_off[j*3+0], pri_rpy_off[j*3+1], pri_rpy_off[j*3+2], Rp);
        float M0p[9], M1p[9], M2p[9];
        mm3(M0p, M0, Rp); mm3(M1p, M1, Rp); mm3(M2p, M2, Rp);

        float Rt[9];
        rpy2r_fast(rpy_track[j*3+0], rpy_track[j*3+1], rpy_track[j*3+2], Rt);
        float M0t[9], M1t[9], M2t[9];
        mm3(M0t, M0p, Rt); mm3(M1t, M1p, Rt); mm3(M2t, M2p, Rt);

#pragma unroll
        for (int i = 0; i < 9; i++) {
            C[i]      = M0[i];  C[9+i]  = M1[i];  C[18+i] = M2[i];
            C[27+i]   = M0p[i]; C[36+i] = M1p[i]; C[45+i] = M2p[i];
            C[54+i]   = M0t[i]; C[63+i] = M1t[i]; C[72+i] = M2t[i];
        }

        float pr[3] = {rev_p_off[j*3+0], rev_p_off[j*3+1], rev_p_off[j*3+2]};
        float pp[3] = {pri_p_off[j*3+0], pri_p_off[j*3+1], pri_p_off[j*3+2]};
        float pax = pri_axis[j*3+0], pay = pri_axis[j*3+1], paz = pri_axis[j*3+2];
        float v[3];
#pragma unroll
        for (int r = 0; r < 3; r++)
            v[r] = Rp[r*3+0]*pax + Rp[r*3+1]*pay + Rp[r*3+2]*paz;
        float ptk[3] = {p_track[j*3+0], p_track[j*3+1], p_track[j*3+2]};
#pragma unroll
        for (int r = 0; r < 3; r++) {
            C[81+r] = M0[r*3+0]*pp[0] + M0[r*3+1]*pp[1] + M0[r*3+2]*pp[2] + pr[r]; // d0
            C[84+r] = M1[r*3+0]*pp[0] + M1[r*3+1]*pp[1] + M1[r*3+2]*pp[2];         // d1
            C[87+r] = M2[r*3+0]*pp[0] + M2[r*3+1]*pp[1] + M2[r*3+2]*pp[2];         // d2
            C[90+r] = M0[r*3+0]*v[0]  + M0[r*3+1]*v[1]  + M0[r*3+2]*v[2];          // e0
            C[93+r] = M1[r*3+0]*v[0]  + M1[r*3+1]*v[1]  + M1[r*3+2]*v[2];          // e1
            C[96+r] = M2[r*3+0]*v[0]  + M2[r*3+1]*v[1]  + M2[r*3+2]*v[2];          // e2
            C[99+r]  = M0p[r*3+0]*ptk[0] + M0p[r*3+1]*ptk[1] + M0p[r*3+2]*ptk[2];  // f0
            C[102+r] = M1p[r*3+0]*ptk[0] + M1p[r*3+1]*ptk[1] + M1p[r*3+2]*ptk[2];  // f1
            C[105+r] = M2p[r*3+0]*ptk[0] + M2p[r*3+1]*ptk[1] + M2p[r*3+2]*ptk[2];  // f2
            C[108+r] = pr[r];
        }
    }
    __syncthreads();

    // ---- phase 1: local chain (one mm3 per joint) ----
    float R[9] = {1.f,0.f,0.f, 0.f,1.f,0.f, 0.f,0.f,1.f};
    float p[3] = {0.f, 0.f, 0.f};
#pragma unroll
    for (int i = 0; i < JPS; i++) {
        const float* C = sC + (s * JPS + i) * CPJ;
        float Rs2[9];
        fold9(Rs2, C, 27, 36, 45, sn[i], ic[i]);
        float u[3];
#pragma unroll
        for (int r = 0; r < 3; r++) {
            float g = fmaf(sn[i], C[93+r], fmaf(ic[i], C[96+r], C[90+r]));
            u[r] = fmaf(qp[i], g, fmaf(sn[i], C[84+r], fmaf(ic[i], C[87+r], C[81+r])));
        }
        float Rn[9], pn[3];
        mm3(Rn, R, Rs2);
        matvec_add(pn, R, u, p);
#pragma unroll
        for (int t = 0; t < 9; t++) R[t] = Rn[t];
        p[0] = pn[0]; p[1] = pn[1]; p[2] = pn[2];
    }

    // ---- phase 2: exclusive prefix within 4-lane group via shfl ----
    float P[9] = {1.f,0.f,0.f, 0.f,1.f,0.f, 0.f,0.f,1.f};
    float pp[3] = {0.f, 0.f, 0.f};
    int base = lane & ~3;
#pragma unroll
    for (int k = 0; k < 3; k++) {
        float Lr[9], Lp[3];
#pragma unroll
        for (int t = 0; t < 9; t++) Lr[t] = __shfl_sync(0xffffffffu, R[t], base + k);
#pragma unroll
        for (int t = 0; t < 3; t++) Lp[t] = __shfl_sync(0xffffffffu, p[t], base + k);
        if (k < s) {
            float pn[3];
            matvec_add(pn, P, Lp, pp);
            float Rn[9];
            mm3(Rn, P, Lr);
#pragma unroll
            for (int t = 0; t < 9; t++) P[t] = Rn[t];
            pp[0] = pn[0]; pp[1] = pn[1]; pp[2] = pn[2];
        }
    }

    // ---- phase 3: all outputs as independent products of R ----
    float* regA = sStage[w];
    float* regB = sStage[w] + REGSZ;
    float* regC = sStage[w] + 2 * REGSZ;
    float* outTrk = out;
    float* outRev = out + (size_t)B * 160;
    float* outPri = out + (size_t)B * 480;

#pragma unroll
    for (int t = 0; t < 9; t++) R[t] = P[t];
    p[0] = pp[0]; p[1] = pp[1]; p[2] = pp[2];

    const float4 hom = make_float4(0.f, 0.f, 0.f, 1.f);

#pragma unroll
    for (int i = 0; i < JPS; i++) {
        const float* C = sC + (s * JPS + i) * CPJ;

        // rev frame: R1 = R@fold(M0..), p1 = R@p_rev + p
        {
            float Rs[9];
            fold9(Rs, C, 0, 9, 18, sn[i], ic[i]);
            float R1[9], p1[3];
            mm3(R1, R, Rs);
            matvec_add(p1, R, C + 108, p);
            stage12(regA + lane * 12, R1, p1);
        }

        // pri frame: R2 = R@fold(M0p..), p2 = R@u + p   (chain update)
        float R2[9], p2[3];
        {
            float Rs2[9];
            fold9(Rs2, C, 27, 36, 45, sn[i], ic[i]);
            float u[3];
#pragma unroll
            for (int r = 0; r < 3; r++) {
                float g = fmaf(sn[i], C[93+r], fmaf(ic[i], C[96+r], C[90+r]));
                u[r] = fmaf(qp[i], g, fmaf(sn[i], C[84+r], fmaf(ic[i], C[87+r], C[81+r])));
            }
            mm3(R2, R, Rs2);
            matvec_add(p2, R, u, p);
            stage12(regB + lane * 12, R2, p2);
        }

        // track frame (owner lanes): Rt = R@fold(M0t..), pt = R@ut + p2
        bool owner = (((s ^ i) & 1) == 0);
        if (owner) {
            float Rs3[9];
            fold9(Rs3, C, 54, 63, 72, sn[i], ic[i]);
            float ut[3];
#pragma unroll
            for (int r = 0; r < 3; r++)
                ut[r] = fmaf(sn[i], C[102+r], fmaf(ic[i], C[105+r], C[99+r]));
            float Rt[9], pt[3];
            mm3(Rt, R, Rs3);
            matvec_add(pt, R, ut, p2);
            stage12(regC + lane * 12, Rt, pt);
        }

        // chain advance
#pragma unroll
        for (int t = 0; t < 9; t++) R[t] = R2[t];
        p[0] = p2[0]; p[1] = p2[1]; p[2] = p2[2];

        __syncwarp();

        // drain rev + pri (R12 mapping)
#pragma unroll
        for (int k = 0; k < 4; k++) {
            int c = k * 32 + lane, idx = c >> 2, m = c & 3;
            int bbd = idx >> 2, s2 = idx & 3;
            int gbd = wb0 + bbd; if (gbd >= B) gbd = B - 1;
            size_t d = ((size_t)gbd * J + 5 * s2 + i) * 16 + 4 * m;
            float4 vr = (m < 3) ? *(const float4*)(regA + idx * 12 + 4 * m) : hom;
            float4 vp = (m < 3) ? *(const float4*)(regB + idx * 12 + 4 * m) : hom;
            *(float4*)(outRev + d) = vr;
            *(float4*)(outPri + d) = vp;
        }
        // drain track
#pragma unroll
        for (int k = 0; k < 2; k++) {
            int c = k * 32 + lane, idx16 = c >> 2, m = c & 3;
            int bbd = idx16 >> 1, pos = idx16 & 1;
            int s2 = (i & 1) + 2 * pos;
            int src = bbd * 4 + s2;
            int slot = (5 * s2 + i) >> 1;
            int gbd = wb0 + bbd; if (gbd >= B) gbd = B - 1;
            float4 v = (m < 3) ? *(const float4*)(regC + src * 12 + 4 * m) : hom;
            *(float4*)(outTrk + ((size_t)gbd * 10 + slot) * 16 + 4 * m) = v;
        }
        __syncwarp();
    }
}

extern "C" void kernel_launch(void* const* d_in, const int* in_sizes, int n_in,
                              void* d_out, int out_size) {
    const float* rev_q       = (const float*)d_in[0];
    const float* pri_q       = (const float*)d_in[1];
    const float* rev_p_off   = (const float*)d_in[2];
    const float* rev_rpy_off = (const float*)d_in[3];
    const float* pri_p_off   = (const float*)d_in[4];
    const float* pri_rpy_off = (const float*)d_in[5];
    const float* rev_axis    = (const float*)d_in[6];
    const float* pri_axis    = (const float*)d_in[7];
    const float* p_track     = (const float*)d_in[8];
    const float* rpy_track   = (const float*)d_in[9];
    float* out = (float*)d_out;

    int B = in_sizes[0] / J;
    int grid = (B + 31) / 32;
    fk_kernel<<<grid, 128>>>(rev_q, pri_q,
                             rev_p_off, rev_rpy_off, pri_p_off, pri_rpy_off,
                             rev_axis, pri_axis, p_track, rpy_track, out, B);
}

// round 15
// speedup vs baseline: 1.1498x; 1.1498x over previous
#include <cuda_runtime.h>
#include <math.h>

#define J 20
#define JPS 5
#define CONST_PER_J 57
#define REGSZ 384
// per joint: M0[9]@0, M1[9]@9, M2[9]@18, p_rev[3]@27,
//            Rpri[9]@30, v_pri[3]@39, p_pri[3]@42, Rtrk[9]@45, p_trk[3]@54

__device__ __forceinline__ void rpy2r_fast(float r, float p, float y, float* R) {
    float cr, sr, cp, sp, cy, sy;
    __sincosf(r, &sr, &cr);
    __sincosf(p, &sp, &cp);
    __sincosf(y, &sy, &cy);
    R[0] = cy * cp; R[1] = cy * sp * sr - sy * cr; R[2] = cy * sp * cr + sy * sr;
    R[3] = sy * cp; R[4] = sy * sp * sr + cy * cr; R[5] = sy * sp * cr - cy * sr;
    R[6] = -sp;     R[7] = cp * sr;                R[8] = cp * cr;
}

__device__ __forceinline__ void mm3(float* D, const float* A, const float* B) {
#pragma unroll
    for (int r = 0; r < 3; r++)
#pragma unroll
        for (int c = 0; c < 3; c++)
            D[r * 3 + c] = fmaf(A[r * 3 + 0], B[0 * 3 + c],
                           fmaf(A[r * 3 + 1], B[1 * 3 + c],
                                A[r * 3 + 2] * B[2 * 3 + c]));
}

__device__ __forceinline__ void joint_apply_c(const float* C, float s, float ic, float qp,
                                              float R[9], float p[3],
                                              float R1[9], float p1[3]) {
    float Rs[9];
#pragma unroll
    for (int i = 0; i < 9; i++)
        Rs[i] = fmaf(s, C[9 + i], fmaf(ic, C[18 + i], C[i]));
    mm3(R1, R, Rs);
#pragma unroll
    for (int r = 0; r < 3; r++)
        p1[r] = fmaf(R[r * 3 + 0], C[27],
                fmaf(R[r * 3 + 1], C[28],
                fmaf(R[r * 3 + 2], C[29], p[r])));
    float ps0 = fmaf(qp, C[39], C[42]);
    float ps1 = fmaf(qp, C[40], C[43]);
    float ps2 = fmaf(qp, C[41], C[44]);
    float R2[9];
    mm3(R2, R1, C + 30);
#pragma unroll
    for (int r = 0; r < 3; r++)
        p[r] = fmaf(R1[r * 3 + 0], ps0,
               fmaf(R1[r * 3 + 1], ps1,
               fmaf(R1[r * 3 + 2], ps2, p1[r])));
#pragma unroll
    for (int i = 0; i < 9; i++) R[i] = R2[i];
}

__device__ __forceinline__ void stage12(float* dst, const float R[9], const float p[3]) {
    float4* sp = (float4*)dst;
    sp[0] = make_float4(R[0], R[1], R[2], p[0]);
    sp[1] = make_float4(R[3], R[4], R[5], p[1]);
    sp[2] = make_float4(R[6], R[7], R[8], p[2]);
}

__global__ void __launch_bounds__(128, 7)
fk_kernel(const float* __restrict__ rev_q, const float* __restrict__ pri_q,
          const float* __restrict__ rev_p_off, const float* __restrict__ rev_rpy_off,
          const float* __restrict__ pri_p_off, const float* __restrict__ pri_rpy_off,
          const float* __restrict__ rev_axis, const float* __restrict__ pri_axis,
          const float* __restrict__ p_track, const float* __restrict__ rpy_track,
          float* __restrict__ out, int B) {
    __shared__ float sC[J * CONST_PER_J];
    __shared__ float sStage[4][6 * REGSZ];   // per warp: {rev,pri,trk} x 2 buffers

    int tid  = threadIdx.x;
    int lane = tid & 31;
    int w    = tid >> 5;
    int bb   = lane >> 2;
    int s    = lane & 3;
    int wb0  = blockIdx.x * 32 + w * 8;
    int gb   = wb0 + bb; if (gb >= B) gb = B - 1;

    // q loads + trig early (overlap with const prep)
    float sn[JPS], ic[JPS], qp[JPS];
#pragma unroll
    for (int i = 0; i < JPS; i++) {
        float q = rev_q[(size_t)gb * J + s * JPS + i];
        float c;
        __sincosf(q, &sn[i], &c);
        ic[i] = 1.f - c;
        qp[i] = pri_q[(size_t)gb * J + s * JPS + i];
    }

    // ---- in-block constant prep (threads 0..19), R12-identical ----
    if (tid < J) {
        int j = tid;
        float* C = sC + j * CONST_PER_J;
        float Ro[9];
        rpy2r_fast(rev_rpy_off[j*3+0], rev_rpy_off[j*3+1], rev_rpy_off[j*3+2], Ro);
        float ax = rev_axis[j*3+0], ay = rev_axis[j*3+1], az = rev_axis[j*3+2];
        float n = sqrtf(ax*ax + ay*ay + az*az) + 1e-12f;
        ax /= n; ay /= n; az /= n;
        float K[9]  = {0.f, -az, ay,  az, 0.f, -ax,  -ay, ax, 0.f};
        float K2[9]; mm3(K2, K, K);
        float M1[9], M2[9]; mm3(M1, Ro, K); mm3(M2, Ro, K2);
#pragma unroll
        for (int i = 0; i < 9; i++) { C[i] = Ro[i]; C[9+i] = M1[i]; C[18+i] = M2[i]; }
        C[27] = rev_p_off[j*3+0]; C[28] = rev_p_off[j*3+1]; C[29] = rev_p_off[j*3+2];

        float Rp[9];
        rpy2r_fast(pri_rpy_off[j*3+0], pri_rpy_off[j*3+1], pri_rpy_off[j*3+2], Rp);
#pragma unroll
        for (int i = 0; i < 9; i++) C[30+i] = Rp[i];
        float pax = pri_axis[j*3+0], pay = pri_axis[j*3+1], paz = pri_axis[j*3+2];
#pragma unroll
        for (int r = 0; r < 3; r++)
            C[39+r] = Rp[r*3+0]*pax + Rp[r*3+1]*pay + Rp[r*3+2]*paz;
        C[42] = pri_p_off[j*3+0]; C[43] = pri_p_off[j*3+1]; C[44] = pri_p_off[j*3+2];

        float Rt[9];
        rpy2r_fast(rpy_track[j*3+0], rpy_track[j*3+1], rpy_track[j*3+2], Rt);
#pragma unroll
        for (int i = 0; i < 9; i++) C[45+i] = Rt[i];
        C[54] = p_track[j*3+0]; C[55] = p_track[j*3+1]; C[56] = p_track[j*3+2];
    }
    __syncthreads();

    // ---- phase 1: local segment product ----
    float R[9] = {1.f,0.f,0.f, 0.f,1.f,0.f, 0.f,0.f,1.f};
    float p[3] = {0.f, 0.f, 0.f};
#pragma unroll
    for (int i = 0; i < JPS; i++) {
        const float* C = sC + (s * JPS + i) * CONST_PER_J;
        float R1[9], p1[3];
        joint_apply_c(C, sn[i], ic[i], qp[i], R, p, R1, p1);
    }

    // ---- phase 2: exclusive prefix within 4-lane group via shfl ----
    float P[9] = {1.f,0.f,0.f, 0.f,1.f,0.f, 0.f,0.f,1.f};
    float pp[3] = {0.f, 0.f, 0.f};
    int base = lane & ~3;
#pragma unroll
    for (int k = 0; k < 3; k++) {
        float Lr[9], Lp[3];
#pragma unroll
        for (int t = 0; t < 9; t++) Lr[t] = __shfl_sync(0xffffffffu, R[t], base + k);
#pragma unroll
        for (int t = 0; t < 3; t++) Lp[t] = __shfl_sync(0xffffffffu, p[t], base + k);
        if (k < s) {
            float pn[3];
#pragma unroll
            for (int r = 0; r < 3; r++)
                pn[r] = fmaf(P[r*3+0], Lp[0],
                        fmaf(P[r*3+1], Lp[1],
                        fmaf(P[r*3+2], Lp[2], pp[r])));
            float Rn[9];
            mm3(Rn, P, Lr);
#pragma unroll
            for (int t = 0; t < 9; t++) P[t] = Rn[t];
            pp[0] = pn[0]; pp[1] = pn[1]; pp[2] = pn[2];
        }
    }

    // ---- phase 3: re-run from prefix, double-buffered single-sync emits ----
    float* outTrk = out;
    float* outRev = out + (size_t)B * 160;
    float* outPri = out + (size_t)B * 480;

#pragma unroll
    for (int t = 0; t < 9; t++) R[t] = P[t];
    p[0] = pp[0]; p[1] = pp[1]; p[2] = pp[2];

    const float4 hom = make_float4(0.f, 0.f, 0.f, 1.f);

#pragma unroll
    for (int i = 0; i < JPS; i++) {
        float* buf  = sStage[w] + (i & 1) * 3 * REGSZ;
        float* regA = buf;               // rev
        float* regB = buf + REGSZ;       // pri
        float* regC = buf + 2 * REGSZ;   // trk

        int j = s * JPS + i;
        const float* C = sC + j * CONST_PER_J;
        float R1[9], p1[3];
        joint_apply_c(C, sn[i], ic[i], qp[i], R, p, R1, p1);

        stage12(regA + lane * 12, R1, p1);
        stage12(regB + lane * 12, R, p);
        bool owner = (((s ^ i) & 1) == 0);   // j = 5s+i even
        if (owner) {
            float Rt[9], pt[3];
            mm3(Rt, R, C + 45);
#pragma unroll
            for (int r = 0; r < 3; r++)
                pt[r] = fmaf(R[r*3+0], C[54],
                        fmaf(R[r*3+1], C[55],
                        fmaf(R[r*3+2], C[56], p[r])));
            stage12(regC + lane * 12, Rt, pt);
        }
        __syncwarp();

        // drain rev + pri
#pragma unroll
        for (int k = 0; k < 4; k++) {
            int c = k * 32 + lane, idx = c >> 2, m = c & 3;
            int bbd = idx >> 2, s2 = idx & 3;
            int gbd = wb0 + bbd; if (gbd >= B) gbd = B - 1;
            size_t d = ((size_t)gbd * J + 5 * s2 + i) * 16 + 4 * m;
            float4 vr = (m < 3) ? *(const float4*)(regA + idx * 12 + 4 * m) : hom;
            float4 vp = (m < 3) ? *(const float4*)(regB + idx * 12 + 4 * m) : hom;
            *(float4*)(outRev + d) = vr;
            *(float4*)(outPri + d) = vp;
        }
        // drain track
#pragma unroll
        for (int k = 0; k < 2; k++) {
            int c = k * 32 + lane, idx16 = c >> 2, m = c & 3;
            int bbd = idx16 >> 1, pos = idx16 & 1;
            int s2 = (i & 1) + 2 * pos;
            int src = bbd * 4 + s2;
            int slot = (5 * s2 + i) >> 1;
            int gbd = wb0 + bbd; if (gbd >= B) gbd = B - 1;
            float4 v = (m < 3) ? *(const float4*)(regC + src * 12 + 4 * m) : hom;
            *(float4*)(outTrk + ((size_t)gbd * 10 + slot) * 16 + 4 * m) = v;
        }
        // no trailing syncwarp: next iteration stages into the other buffer
    }
}

extern "C" void kernel_launch(void* const* d_in, const int* in_sizes, int n_in,
                              void* d_out, int out_size) {
    const float* rev_q       = (const float*)d_in[0];
    const float* pri_q       = (const float*)d_in[1];
    const float* rev_p_off   = (const float*)d_in[2];
    const float* rev_rpy_off = (const float*)d_in[3];
    const float* pri_p_off   = (const float*)d_in[4];
    const float* pri_rpy_off = (const float*)d_in[5];
    const float* rev_axis    = (const float*)d_in[6];
    const float* pri_axis    = (const float*)d_in[7];
    const float* p_track     = (const float*)d_in[8];
    const float* rpy_track   = (const float*)d_in[9];
    float* out = (float*)d_out;

    int B = in_sizes[0] / J;
    int grid = (B + 31) / 32;
    fk_kernel<<<grid, 128>>>(rev_q, pri_q,
                             rev_p_off, rev_rpy_off, pri_p_off, pri_rpy_off,
                             rev_axis, pri_axis, p_track, rpy_track, out, B);
}

// round 16
// speedup vs baseline: 1.1511x; 1.0012x over previous
#include <cuda_runtime.h>
#include <math.h>

#define J 20
#define JPS 5
#define CONST_PER_J 57
#define REGSZ 384
// per joint: M0[9]@0, M1[9]@9, M2[9]@18, p_rev[3]@27,
//            Rpri[9]@30, v_pri[3]@39, p_pri[3]@42, Rtrk[9]@45, p_trk[3]@54

__device__ __forceinline__ void rpy2r_fast(float r, float p, float y, float* R) {
    float cr, sr, cp, sp, cy, sy;
    __sincosf(r, &sr, &cr);
    __sincosf(p, &sp, &cp);
    __sincosf(y, &sy, &cy);
    R[0] = cy * cp; R[1] = cy * sp * sr - sy * cr; R[2] = cy * sp * cr + sy * sr;
    R[3] = sy * cp; R[4] = sy * sp * sr + cy * cr; R[5] = sy * sp * cr - cy * sr;
    R[6] = -sp;     R[7] = cp * sr;                R[8] = cp * cr;
}

__device__ __forceinline__ void mm3(float* D, const float* A, const float* B) {
#pragma unroll
    for (int r = 0; r < 3; r++)
#pragma unroll
        for (int c = 0; c < 3; c++)
            D[r * 3 + c] = fmaf(A[r * 3 + 0], B[0 * 3 + c],
                           fmaf(A[r * 3 + 1], B[1 * 3 + c],
                                A[r * 3 + 2] * B[2 * 3 + c]));
}

__device__ __forceinline__ void joint_apply_c(const float* C, float s, float ic, float qp,
                                              float R[9], float p[3],
                                              float R1[9], float p1[3]) {
    float Rs[9];
#pragma unroll
    for (int i = 0; i < 9; i++)
        Rs[i] = fmaf(s, C[9 + i], fmaf(ic, C[18 + i], C[i]));
    mm3(R1, R, Rs);
#pragma unroll
    for (int r = 0; r < 3; r++)
        p1[r] = fmaf(R[r * 3 + 0], C[27],
                fmaf(R[r * 3 + 1], C[28],
                fmaf(R[r * 3 + 2], C[29], p[r])));
    float ps0 = fmaf(qp, C[39], C[42]);
    float ps1 = fmaf(qp, C[40], C[43]);
    float ps2 = fmaf(qp, C[41], C[44]);
    float R2[9];
    mm3(R2, R1, C + 30);
#pragma unroll
    for (int r = 0; r < 3; r++)
        p[r] = fmaf(R1[r * 3 + 0], ps0,
               fmaf(R1[r * 3 + 1], ps1,
               fmaf(R1[r * 3 + 2], ps2, p1[r])));
#pragma unroll
    for (int i = 0; i < 9; i++) R[i] = R2[i];
}

__device__ __forceinline__ void stage12(float* dst, const float R[9], const float p[3]) {
    float4* sp = (float4*)dst;
    sp[0] = make_float4(R[0], R[1], R[2], p[0]);
    sp[1] = make_float4(R[3], R[4], R[5], p[1]);
    sp[2] = make_float4(R[6], R[7], R[8], p[2]);
}

__global__ void __launch_bounds__(128, 6)
fk_kernel(const float* __restrict__ rev_q, const float* __restrict__ pri_q,
          const float* __restrict__ rev_p_off, const float* __restrict__ rev_rpy_off,
          const float* __restrict__ pri_p_off, const float* __restrict__ pri_rpy_off,
          const float* __restrict__ rev_axis, const float* __restrict__ pri_axis,
          const float* __restrict__ p_track, const float* __restrict__ rpy_track,
          float* __restrict__ out, int B) {
    __shared__ float sC[J * CONST_PER_J];
    __shared__ float sStage[4][5 * REGSZ];   // rev0,pri0,rev1,pri1,trk

    int tid  = threadIdx.x;
    int lane = tid & 31;
    int w    = tid >> 5;
    int bb   = lane >> 2;
    int s    = lane & 3;
    int wb0  = blockIdx.x * 32 + w * 8;
    int gb   = wb0 + bb; if (gb >= B) gb = B - 1;

    // q loads + trig early (overlap with const prep)
    float sn[JPS], ic[JPS], qp[JPS];
#pragma unroll
    for (int i = 0; i < JPS; i++) {
        float q = rev_q[(size_t)gb * J + s * JPS + i];
        float c;
        __sincosf(q, &sn[i], &c);
        ic[i] = 1.f - c;
        qp[i] = pri_q[(size_t)gb * J + s * JPS + i];
    }

    // ---- in-block constant prep (threads 0..19), R12-identical ----
    if (tid < J) {
        int j = tid;
        float* C = sC + j * CONST_PER_J;
        float Ro[9];
        rpy2r_fast(rev_rpy_off[j*3+0], rev_rpy_off[j*3+1], rev_rpy_off[j*3+2], Ro);
        float ax = rev_axis[j*3+0], ay = rev_axis[j*3+1], az = rev_axis[j*3+2];
        float n = sqrtf(ax*ax + ay*ay + az*az) + 1e-12f;
        ax /= n; ay /= n; az /= n;
        float K[9]  = {0.f, -az, ay,  az, 0.f, -ax,  -ay, ax, 0.f};
        float K2[9]; mm3(K2, K, K);
        float M1[9], M2[9]; mm3(M1, Ro, K); mm3(M2, Ro, K2);
#pragma unroll
        for (int i = 0; i < 9; i++) { C[i] = Ro[i]; C[9+i] = M1[i]; C[18+i] = M2[i]; }
        C[27] = rev_p_off[j*3+0]; C[28] = rev_p_off[j*3+1]; C[29] = rev_p_off[j*3+2];

        float Rp[9];
        rpy2r_fast(pri_rpy_off[j*3+0], pri_rpy_off[j*3+1], pri_rpy_off[j*3+2], Rp);
#pragma unroll
        for (int i = 0; i < 9; i++) C[30+i] = Rp[i];
        float pax = pri_axis[j*3+0], pay = pri_axis[j*3+1], paz = pri_axis[j*3+2];
#pragma unroll
        for (int r = 0; r < 3; r++)
            C[39+r] = Rp[r*3+0]*pax + Rp[r*3+1]*pay + Rp[r*3+2]*paz;
        C[42] = pri_p_off[j*3+0]; C[43] = pri_p_off[j*3+1]; C[44] = pri_p_off[j*3+2];

        float Rt[9];
        rpy2r_fast(rpy_track[j*3+0], rpy_track[j*3+1], rpy_track[j*3+2], Rt);
#pragma unroll
        for (int i = 0; i < 9; i++) C[45+i] = Rt[i];
        C[54] = p_track[j*3+0]; C[55] = p_track[j*3+1]; C[56] = p_track[j*3+2];
    }
    __syncthreads();

    // ---- phase 1: local segment product ----
    float R[9] = {1.f,0.f,0.f, 0.f,1.f,0.f, 0.f,0.f,1.f};
    float p[3] = {0.f, 0.f, 0.f};
#pragma unroll
    for (int i = 0; i < JPS; i++) {
        const float* C = sC + (s * JPS + i) * CONST_PER_J;
        float R1[9], p1[3];
        joint_apply_c(C, sn[i], ic[i], qp[i], R, p, R1, p1);
    }

    // ---- phase 2: exclusive prefix within 4-lane group via shfl ----
    float P[9] = {1.f,0.f,0.f, 0.f,1.f,0.f, 0.f,0.f,1.f};
    float pp[3] = {0.f, 0.f, 0.f};
    int base = lane & ~3;
#pragma unroll
    for (int k = 0; k < 3; k++) {
        float Lr[9], Lp[3];
#pragma unroll
        for (int t = 0; t < 9; t++) Lr[t] = __shfl_sync(0xffffffffu, R[t], base + k);
#pragma unroll
        for (int t = 0; t < 3; t++) Lp[t] = __shfl_sync(0xffffffffu, p[t], base + k);
        if (k < s) {
            float pn[3];
#pragma unroll
            for (int r = 0; r < 3; r++)
                pn[r] = fmaf(P[r*3+0], Lp[0],
                        fmaf(P[r*3+1], Lp[1],
                        fmaf(P[r*3+2], Lp[2], pp[r])));
            float Rn[9];
            mm3(Rn, P, Lr);
#pragma unroll
            for (int t = 0; t < 9; t++) P[t] = Rn[t];
            pp[0] = pn[0]; pp[1] = pn[1]; pp[2] = pn[2];
        }
    }

    // ---- phase 3: re-run from prefix; rev/pri double-buffered, trk fenced ----
    float* outTrk = out;
    float* outRev = out + (size_t)B * 160;
    float* outPri = out + (size_t)B * 480;
    float* regC = sStage[w] + 4 * REGSZ;   // shared trk region

#pragma unroll
    for (int t = 0; t < 9; t++) R[t] = P[t];
    p[0] = pp[0]; p[1] = pp[1]; p[2] = pp[2];

    const float4 hom = make_float4(0.f, 0.f, 0.f, 1.f);

#pragma unroll
    for (int i = 0; i < JPS; i++) {
        float* buf  = sStage[w] + (i & 1) * 2 * REGSZ;
        float* regA = buf;               // rev
        float* regB = buf + REGSZ;       // pri

        int j = s * JPS + i;
        const float* C = sC + j * CONST_PER_J;
        float R1[9], p1[3];
        joint_apply_c(C, sn[i], ic[i], qp[i], R, p, R1, p1);

        stage12(regA + lane * 12, R1, p1);
        stage12(regB + lane * 12, R, p);
        bool owner = (((s ^ i) & 1) == 0);   // j = 5s+i even
        if (owner) {
            float Rt[9], pt[3];
            mm3(Rt, R, C + 45);
#pragma unroll
            for (int r = 0; r < 3; r++)
                pt[r] = fmaf(R[r*3+0], C[54],
                        fmaf(R[r*3+1], C[55],
                        fmaf(R[r*3+2], C[56], p[r])));
            stage12(regC + lane * 12, Rt, pt);
        }
        __syncwarp();

        // drain track first (shared region; fenced by the next syncwarp)
#pragma unroll
        for (int k = 0; k < 2; k++) {
            int c = k * 32 + lane, idx16 = c >> 2, m = c & 3;
            int bbd = idx16 >> 1, pos = idx16 & 1;
            int s2 = (i & 1) + 2 * pos;
            int src = bbd * 4 + s2;
            int slot = (5 * s2 + i) >> 1;
            int gbd = wb0 + bbd; if (gbd >= B) gbd = B - 1;
            float4 v = (m < 3) ? *(const float4*)(regC + src * 12 + 4 * m) : hom;
            *(float4*)(outTrk + ((size_t)gbd * 10 + slot) * 16 + 4 * m) = v;
        }
        __syncwarp();

        // drain rev + pri (double-buffered: safe to overlap into next iteration)
#pragma unroll
        for (int k = 0; k < 4; k++) {
            int c = k * 32 + lane, idx = c >> 2, m = c & 3;
            int bbd = idx >> 2, s2 = idx & 3;
            int gbd = wb0 + bbd; if (gbd >= B) gbd = B - 1;
            size_t d = ((size_t)gbd * J + 5 * s2 + i) * 16 + 4 * m;
            float4 vr = (m < 3) ? *(const float4*)(regA + idx * 12 + 4 * m) : hom;
            float4 vp = (m < 3) ? *(const float4*)(regB + idx * 12 + 4 * m) : hom;
            *(float4*)(outRev + d) = vr;
            *(float4*)(outPri + d) = vp;
        }
        // no trailing syncwarp
    }
}

extern "C" void kernel_launch(void* const* d_in, const int* in_sizes, int n_in,
                              void* d_out, int out_size) {
    const float* rev_q       = (const float*)d_in[0];
    const float* pri_q       = (const float*)d_in[1];
    const float* rev_p_off   = (const float*)d_in[2];
    const float* rev_rpy_off = (const float*)d_in[3];
    const float* pri_p_off   = (const float*)d_in[4];
    const float* pri_rpy_off = (const float*)d_in[5];
    const float* rev_axis    = (const float*)d_in[6];
    const float* pri_axis    = (const float*)d_in[7];
    const float* p_track     = (const float*)d_in[8];
    const float* rpy_track   = (const float*)d_in[9];
    float* out = (float*)d_out;

    int B = in_sizes[0] / J;
    int grid = (B + 31) / 32;
    fk_kernel<<<grid, 128>>>(rev_q, pri_q,
                             rev_p_off, rev_rpy_off, pri_p_off, pri_rpy_off,
                             rev_axis, pri_axis, p_track, rpy_track, out, B);
}